// round 17
// baseline (speedup 1.0000x reference)
#include <cuda_runtime.h>
#include <math.h>
#include <stdint.h>

// Problem shapes (fixed for this bench)
#define BB 4
#define TT 512
#define SS 1024
#define HH 768
#define VV 50257

// Vocab split: two CTAs per (b,t) row (proven fastest copy shape).
#define VLO1   25129                 // half0 = [0,25129), half1 = [25129,50257)
#define VPADH  25136                 // pad(<=3) + 25129, rounded up
#define SMEM_FLOATS (VPADH + 32)
#define SMEM_BYTES  (SMEM_FLOATS * 4)

#define NROWS (BB * TT)              // 2048
#define NU    (BB * SS)              // 4096 u rows
#define NUV   (NU + NROWS)           // 6144 projection rows

// Scratch for the collapsed p_gen projections (device globals: no allocation).
__device__ float g_u[NU];            // u[b,s] = src[b,s,:] . W_pgen[:H]
__device__ float g_v[NROWS];         // v[b,t] = tgt[b,t,:] . W_pgen[H:] + bias

// ---------------------------------------------------------------------------
// Kernel 1: projections — ONE 192-thread block per row (192 x float4 = 768).
// 6144 blocks = 1.18M threads: fills the chip, every load coalesced, so the
// kernel is bandwidth-bound (~19MB reads) instead of latency-bound like the
// warp-per-row versions (R12: 27% DRAM, 0.65 waves).
// ---------------------------------------------------------------------------
__global__ __launch_bounds__(192)
void pgen_prep_kernel(const float* __restrict__ src,
                      const float* __restrict__ tgt,
                      const float* __restrict__ W,
                      const float* __restrict__ bias)
{
#if __CUDA_ARCH__ >= 900
    cudaTriggerProgrammaticLaunchCompletion();
#endif
    __shared__ float red[6];
    const int rr   = blockIdx.x;           // projection row 0..6143
    const int tid  = threadIdx.x;          // 0..191
    const int lane = tid & 31;
    const int wid  = tid >> 5;             // 0..5

    const float4* x;
    const float4* w;
    if (rr < NU) {
        x = reinterpret_cast<const float4*>(src + (size_t)rr * HH);
        w = reinterpret_cast<const float4*>(W);
    } else {
        x = reinterpret_cast<const float4*>(tgt + (size_t)(rr - NU) * HH);
        w = reinterpret_cast<const float4*>(W + HH);
    }

    const float4 a = x[tid];
    const float4 b = w[tid];
    float acc = a.x * b.x + a.y * b.y + a.z * b.z + a.w * b.w;

    #pragma unroll
    for (int o = 16; o; o >>= 1) acc += __shfl_xor_sync(0xffffffffu, acc, o);
    if (lane == 0) red[wid] = acc;
    __syncthreads();

    if (tid == 0) {
        float s = red[0] + red[1] + red[2] + red[3] + red[4] + red[5];
        if (rr < NU) g_u[rr] = s;
        else         g_v[rr - NU] = s + bias[0];
    }
}

// ---------------------------------------------------------------------------
// Kernel 2 (byte-identical to R16 — best measured copy: 62.0us, 73.4% DRAM):
// two CTAs per (b,t) row.
//   Phase 1: zero ~100KB smem accumulator (STS.128)
//   Phase 2: range-predicated shared atomicAdd scatter
//   Phase 3: ONE bulk-async (TMA) copy smem -> gmem for the half-row
//   Phase 4 (half 0): grid-dep sync on prep, fused p_gen reduction —
//            overlapped with this CTA's own TMA drain.
// ---------------------------------------------------------------------------
__global__ __launch_bounds__(1024, 2)
void copy_logits_kernel(const int* __restrict__ ids,
                        const float* __restrict__ attn,
                        float* __restrict__ out_pgen,
                        float* __restrict__ out_logits)
{
    extern __shared__ float sm[];          // [VPADH] accumulator + [32] reduce
    const int row  = blockIdx.x >> 1;      // b*T + t
    const int half = blockIdx.x & 1;
    const int b    = row >> 9;
    const int tid  = threadIdx.x;

    const int lo = half ? VLO1 : 0;
    const int hi = half ? VV   : VLO1;
    const int n  = hi - lo;

    // Global destination of this half-row; 16B phase decides head & pad.
    float* dst = out_logits + (size_t)row * VV + lo;
    const int head = (int)(((16u - ((uint32_t)(uintptr_t)dst & 15u)) & 15u) >> 2);
    const int pad  = (4 - head) & 3;       // sm[pad+head] is 16B-aligned

    // Phase 1: zero the accumulator (vectorized STS.128).
    float4* sm4 = reinterpret_cast<float4*>(sm);
    const float4 z4 = make_float4(0.f, 0.f, 0.f, 0.f);
    #pragma unroll
    for (int i = tid; i < VPADH / 4; i += 1024) sm4[i] = z4;
    __syncthreads();

    // Phase 2: range-predicated scatter-add. Exactly S=1024 threads, 1 each.
    const float a  = attn[(size_t)row * SS + tid];
    const int   id = ids[b * SS + tid];
    if (id >= lo && id < hi) atomicAdd(&sm[pad + id - lo], a);
    __syncthreads();                       // all atomics complete

    // Phase 3: head/tail scalars + one bulk-async copy for the aligned middle.
    const int nvec = (n - head) >> 2;
    const int tail = head + 4 * nvec;

    if (tid < head)     __stcs(dst + tid, sm[pad + tid]);
    if (tid < n - tail) __stcs(dst + tail + tid, sm[pad + tail + tid]);

    if (tid == 0) {
        asm volatile("fence.proxy.async.shared::cta;" ::: "memory");
        uint32_t saddr;
        asm("{ .reg .u64 t; cvta.to.shared.u64 t, %1; cvt.u32.u64 %0, t; }"
            : "=r"(saddr) : "l"(sm + pad + head));
        asm volatile(
            "cp.async.bulk.global.shared::cta.bulk_group [%0], [%1], %2;"
            :: "l"(dst + head), "r"(saddr), "r"(16 * nvec) : "memory");
        asm volatile("cp.async.bulk.commit_group;" ::: "memory");
    }

    // Phase 4: fused p_gen = sigmoid(attn . u + v), half-0 CTAs only.
    // Runs while this CTA's TMA drain is in flight. Requires prep complete.
    if (half == 0) {
#if __CUDA_ARCH__ >= 900
        cudaGridDependencySynchronize();
#endif
        float part = a * g_u[b * SS + tid];
        #pragma unroll
        for (int o = 16; o; o >>= 1) part += __shfl_xor_sync(0xffffffffu, part, o);
        float* red = sm + VPADH;
        if ((tid & 31) == 0) red[tid >> 5] = part;
        __syncthreads();
        if (tid < 32) {
            float x = red[tid];
            #pragma unroll
            for (int o = 16; o; o >>= 1) x += __shfl_xor_sync(0xffffffffu, x, o);
            if (tid == 0) {
                const float zv = x + g_v[row];
                out_pgen[row] = 1.f / (1.f + __expf(-zv));
            }
        }
    }

    if (tid == 0)
        asm volatile("cp.async.bulk.wait_group 0;" ::: "memory");
}

// ---------------------------------------------------------------------------
// Launch: prep, then copy with Programmatic Dependent Launch (harmless if the
// graph serializes it; the win this round is the 2.5x faster prep).
// ---------------------------------------------------------------------------
extern "C" void kernel_launch(void* const* d_in, const int* in_sizes, int n_in,
                              void* d_out, int out_size)
{
    const int*   ids  = (const int*)  d_in[0];  // [B,S] int32
    const float* attn = (const float*)d_in[1];  // [B,T,S]
    const float* src  = (const float*)d_in[2];  // [B,S,H]
    const float* tgt  = (const float*)d_in[3];  // [B,T,H]
    const float* W    = (const float*)d_in[4];  // [2H,1]
    const float* bias = (const float*)d_in[5];  // [1]

    float* out_pgen   = (float*)d_out;              // [B,T]  (first output)
    float* out_logits = out_pgen + (size_t)BB * TT; // [B,T,V]

    cudaFuncSetAttribute(copy_logits_kernel,
                         cudaFuncAttributeMaxDynamicSharedMemorySize,
                         SMEM_BYTES);

    // One 192-thread block per projection row.
    pgen_prep_kernel<<<NUV, 192>>>(src, tgt, W, bias);

    // Copy kernel with PDL (programmatic stream serialization).
    cudaLaunchConfig_t cfg = {};
    cfg.gridDim          = dim3(NROWS * 2, 1, 1);
    cfg.blockDim         = dim3(1024, 1, 1);
    cfg.dynamicSmemBytes = SMEM_BYTES;
    cfg.stream           = 0;
    cudaLaunchAttribute attr[1];
    attr[0].id = cudaLaunchAttributeProgrammaticStreamSerialization;
    attr[0].val.programmaticStreamSerializationAllowed = 1;
    cfg.attrs    = attr;
    cfg.numAttrs = 1;

    cudaError_t e = cudaLaunchKernelEx(&cfg, copy_logits_kernel,
                                       ids, attn, out_pgen, out_logits);
    if (e != cudaSuccess) {
        (void)cudaGetLastError();   // clear; fall back to plain launch
        copy_logits_kernel<<<NROWS * 2, 1024, SMEM_BYTES>>>(ids, attn,
                                                            out_pgen,
                                                            out_logits);
    }
}